// round 4
// baseline (speedup 1.0000x reference)
#include <cuda_runtime.h>
#include <cuda_fp16.h>
#include <cstdint>

#define NPOS 8192
#define CH 64
#define BM 64
#define BN 64
#define NT (NPOS / BN)
#define LOG2E 1.4426950408889634f

// ---------------- device scratch ----------------
#define TOT_ELEMS (2 * NPOS * CH)
__device__ __half g_hi[TOT_ELEMS];    // [b][n][c] fp16 hi
__device__ __half g_lo[TOT_ELEMS];    // [b][n][c] fp16 lo residual
__device__ __half g_thi[TOT_ELEMS];   // [b][c][n] transposed hi
__device__ __half g_tlo[TOT_ELEMS];   // [b][c][n] transposed lo

// ---------------- helpers ----------------
__device__ __forceinline__ uint32_t smem_u32(const void* p) {
    uint32_t a;
    asm("{ .reg .u64 t; cvta.to.shared.u64 t, %1; cvt.u32.u64 %0, t; }" : "=r"(a) : "l"(p));
    return a;
}
__device__ __forceinline__ float ex2f(float v) {
    float r; asm("ex2.approx.ftz.f32 %0, %1;" : "=f"(r) : "f"(v)); return r;
}
__device__ __forceinline__ uint32_t h2u(__half2 h) { return *reinterpret_cast<uint32_t*>(&h); }

__device__ __forceinline__ void cp_async16(uint32_t dst, const void* src) {
    asm volatile("cp.async.cg.shared.global [%0], [%1], 16;" :: "r"(dst), "l"(src) : "memory");
}
__device__ __forceinline__ void cp_commit() {
    asm volatile("cp.async.commit_group;" ::: "memory");
}
template <int N>
__device__ __forceinline__ void cp_wait() {
    asm volatile("cp.async.wait_group %0;" :: "n"(N) : "memory");
}
__device__ __forceinline__ uint32_t lds32(uint32_t addr) {
    uint32_t v; asm volatile("ld.shared.b32 %0, [%1];" : "=r"(v) : "r"(addr)); return v;
}

// mma.sync m16n8k16 f16 -> f32 accumulate
__device__ __forceinline__ void mma16816(float* d, const uint32_t* a, const uint32_t* b) {
    asm volatile(
        "mma.sync.aligned.m16n8k16.row.col.f32.f16.f16.f32 "
        "{%0,%1,%2,%3}, {%4,%5,%6,%7}, {%8,%9}, {%0,%1,%2,%3};"
        : "+f"(d[0]), "+f"(d[1]), "+f"(d[2]), "+f"(d[3])
        : "r"(a[0]), "r"(a[1]), "r"(a[2]), "r"(a[3]), "r"(b[0]), "r"(b[1]));
}

// ---------------- smem layout (bytes) ----------------
#define KSTR 72     // K tile row stride in halfs (64 + 8 pad)
#define VSTR 72     // Vt tile row stride in halfs (64 + 8 pad)
#define OFF_KHI 0
#define OFF_KLO (BN * KSTR * 2)                  // 9216
#define OFF_VHI (OFF_KLO + BN * KSTR * 2)        // 18432
#define OFF_VLO (OFF_VHI + CH * VSTR * 2)        // 27648
#define BUFSZ   (OFF_VLO + CH * VSTR * 2)        // 36864
#define SMEM_TOTAL (2 * BUFSZ)                   // 73728 -> 2 CTAs/SM

// ---------------- pre-pass: fp32 -> fp16 hi/lo (+ transposed) ----------------
__global__ __launch_bounds__(256) void convert_kernel(const float* __restrict__ x)
{
    __shared__ float t[64][65];
    const int b  = blockIdx.y;
    const int n0 = blockIdx.x * 64;
    const int tid = threadIdx.x;

    const float* xb = x + ((size_t)b * NPOS + n0) * CH;
    __half* ghi = g_hi + ((size_t)b * NPOS + n0) * CH;
    __half* glo = g_lo + ((size_t)b * NPOS + n0) * CH;

    #pragma unroll
    for (int it = 0; it < 4; ++it) {
        int lin = it * 256 + tid;
        int n   = lin >> 4;
        int c4  = (lin & 15) * 4;
        float4 v = *(const float4*)(xb + (size_t)n * CH + c4);
        t[n][c4 + 0] = v.x; t[n][c4 + 1] = v.y; t[n][c4 + 2] = v.z; t[n][c4 + 3] = v.w;
        __half h0 = __float2half_rn(v.x), h1 = __float2half_rn(v.y);
        __half h2 = __float2half_rn(v.z), h3 = __float2half_rn(v.w);
        uint2 hw = make_uint2(h2u(__halves2half2(h0, h1)), h2u(__halves2half2(h2, h3)));
        *(uint2*)(ghi + (size_t)n * CH + c4) = hw;
        __half l0 = __float2half_rn(v.x - __half2float(h0));
        __half l1 = __float2half_rn(v.y - __half2float(h1));
        __half l2 = __float2half_rn(v.z - __half2float(h2));
        __half l3 = __float2half_rn(v.w - __half2float(h3));
        uint2 lw = make_uint2(h2u(__halves2half2(l0, l1)), h2u(__halves2half2(l2, l3)));
        *(uint2*)(glo + (size_t)n * CH + c4) = lw;
    }
    __syncthreads();

    __half* gth = g_thi + (size_t)b * CH * NPOS + n0;
    __half* gtl = g_tlo + (size_t)b * CH * NPOS + n0;
    #pragma unroll
    for (int it = 0; it < 2; ++it) {
        int lin = it * 256 + tid;
        int c  = lin >> 3;
        int n8 = (lin & 7) * 8;
        float f[8];
        #pragma unroll
        for (int e = 0; e < 8; ++e) f[e] = t[n8 + e][c];
        __half hh[8];
        #pragma unroll
        for (int e = 0; e < 8; ++e) hh[e] = __float2half_rn(f[e]);
        uint4 w;
        w.x = h2u(__halves2half2(hh[0], hh[1])); w.y = h2u(__halves2half2(hh[2], hh[3]));
        w.z = h2u(__halves2half2(hh[4], hh[5])); w.w = h2u(__halves2half2(hh[6], hh[7]));
        *(uint4*)(gth + (size_t)c * NPOS + n8) = w;
        __half ll[8];
        #pragma unroll
        for (int e = 0; e < 8; ++e) ll[e] = __float2half_rn(f[e] - __half2float(hh[e]));
        uint4 wl;
        wl.x = h2u(__halves2half2(ll[0], ll[1])); wl.y = h2u(__halves2half2(ll[2], ll[3]));
        wl.z = h2u(__halves2half2(ll[4], ll[5])); wl.w = h2u(__halves2half2(ll[6], ll[7]));
        *(uint4*)(gtl + (size_t)c * NPOS + n8) = wl;
    }
}

// ---------------- main flash-attention kernel (warp-mma, 2 CTA/SM) ----------------
__global__ __launch_bounds__(128, 2) void attn_kernel(
    const float* __restrict__ x,
    const float* __restrict__ gamma_p,
    float* __restrict__ out)
{
    extern __shared__ __align__(128) char smem[];
    const uint32_t sb = smem_u32(smem);
    const int tid  = threadIdx.x;
    const int w    = tid >> 5;
    const int lane = tid & 31;
    const int q4   = lane >> 2;    // t/4
    const int qm   = lane & 3;     // t%4
    const int b    = blockIdx.y;
    const int i0   = blockIdx.x * BM;

    const __half* xhi = g_hi  + (size_t)b * NPOS * CH;
    const __half* xlo = g_lo  + (size_t)b * NPOS * CH;
    const __half* thi = g_thi + (size_t)b * CH * NPOS;
    const __half* tlo = g_tlo + (size_t)b * CH * NPOS;

    // ---- prefetch one KV tile (BN=64 keys) into buffer `buf` ----
    auto prefetch = [&](int jt, int buf) {
        const uint32_t d  = sb + (uint32_t)buf * BUFSZ;
        const int j0 = jt * BN;
        #pragma unroll
        for (int it = 0; it < 4; ++it) {           // K: 64 rows x 8 chunks
            int lin = it * 128 + tid;
            int row = lin >> 3, c16 = (lin & 7) * 8;
            uint32_t so = (uint32_t)(row * KSTR + c16) * 2;
            const size_t go = (size_t)(j0 + row) * CH + c16;
            cp_async16(d + OFF_KHI + so, xhi + go);
            cp_async16(d + OFF_KLO + so, xlo + go);
        }
        #pragma unroll
        for (int it = 0; it < 4; ++it) {           // Vt: 64 ch-rows x 8 chunks
            int lin = it * 128 + tid;
            int row = lin >> 3, c16 = (lin & 7) * 8;
            uint32_t so = (uint32_t)(row * VSTR + c16) * 2;
            const size_t go = (size_t)row * NPOS + j0 + c16;
            cp_async16(d + OFF_VHI + so, thi + go);
            cp_async16(d + OFF_VLO + so, tlo + go);
        }
        cp_commit();
    };

    // ---- Q fragments (hi+lo), loaded once from gmem ----
    uint32_t Qh[4][4], Ql[4][4];
    {
        const int r0 = i0 + w * 16 + q4;
        #pragma unroll
        for (int kc = 0; kc < 4; ++kc) {
            int c = kc * 16 + qm * 2;
            Qh[kc][0] = *(const uint32_t*)(xhi + (size_t)r0 * CH + c);
            Qh[kc][1] = *(const uint32_t*)(xhi + (size_t)(r0 + 8) * CH + c);
            Qh[kc][2] = *(const uint32_t*)(xhi + (size_t)r0 * CH + c + 8);
            Qh[kc][3] = *(const uint32_t*)(xhi + (size_t)(r0 + 8) * CH + c + 8);
            Ql[kc][0] = *(const uint32_t*)(xlo + (size_t)r0 * CH + c);
            Ql[kc][1] = *(const uint32_t*)(xlo + (size_t)(r0 + 8) * CH + c);
            Ql[kc][2] = *(const uint32_t*)(xlo + (size_t)r0 * CH + c + 8);
            Ql[kc][3] = *(const uint32_t*)(xlo + (size_t)(r0 + 8) * CH + c + 8);
        }
    }

    prefetch(0, 0);

    float m0 = -1e30f, m1 = -1e30f, l0 = 0.0f, l1 = 0.0f;
    float O[8][4];
    #pragma unroll
    for (int nb = 0; nb < 8; ++nb)
        #pragma unroll
        for (int e = 0; e < 4; ++e) O[nb][e] = 0.0f;

    for (int jt = 0; jt < NT; ++jt) {
        if (jt + 1 < NT) { prefetch(jt + 1, (jt + 1) & 1); cp_wait<1>(); }
        else             { cp_wait<0>(); }
        __syncthreads();

        const uint32_t kb = sb + (uint32_t)(jt & 1) * BUFSZ;

        // ---- GEMM1: S(16x64) = Qhi*Khi + Qlo*Khi + Qhi*Klo ----
        float S[8][4];
        #pragma unroll
        for (int nb = 0; nb < 8; ++nb)
            #pragma unroll
            for (int e = 0; e < 4; ++e) S[nb][e] = 0.0f;

        #pragma unroll
        for (int kc = 0; kc < 4; ++kc) {
            #pragma unroll
            for (int nb = 0; nb < 8; ++nb) {
                uint32_t ao = kb + (uint32_t)(((nb * 8 + q4) * KSTR + kc * 16 + qm * 2) * 2);
                uint32_t bh[2], bl[2];
                bh[0] = lds32(ao + OFF_KHI);  bh[1] = lds32(ao + OFF_KHI + 16);
                bl[0] = lds32(ao + OFF_KLO);  bl[1] = lds32(ao + OFF_KLO + 16);
                mma16816(S[nb], Qh[kc], bh);
                mma16816(S[nb], Ql[kc], bh);
                mma16816(S[nb], Qh[kc], bl);
            }
        }

        // ---- online softmax ----
        float mx0 = -1e30f, mx1 = -1e30f;
        #pragma unroll
        for (int nb = 0; nb < 8; ++nb) {
            mx0 = fmaxf(mx0, fmaxf(S[nb][0], S[nb][1]));
            mx1 = fmaxf(mx1, fmaxf(S[nb][2], S[nb][3]));
        }
        mx0 = fmaxf(mx0, __shfl_xor_sync(0xffffffffu, mx0, 1));
        mx0 = fmaxf(mx0, __shfl_xor_sync(0xffffffffu, mx0, 2));
        mx1 = fmaxf(mx1, __shfl_xor_sync(0xffffffffu, mx1, 1));
        mx1 = fmaxf(mx1, __shfl_xor_sync(0xffffffffu, mx1, 2));
        float mn0 = fmaxf(m0, mx0), mn1 = fmaxf(m1, mx1);
        float c0 = ex2f((m0 - mn0) * LOG2E), c1 = ex2f((m1 - mn1) * LOG2E);
        m0 = mn0; m1 = mn1;

        float s0 = 0.0f, s1 = 0.0f;
        uint32_t Ph[4][4], Pl[4][4];
        #pragma unroll
        for (int kk = 0; kk < 4; ++kk) {
            #pragma unroll
            for (int t = 0; t < 2; ++t) {
                int nb = 2 * kk + t;
                float e0 = ex2f((S[nb][0] - mn0) * LOG2E);
                float e1 = ex2f((S[nb][1] - mn0) * LOG2E);
                float e2 = ex2f((S[nb][2] - mn1) * LOG2E);
                float e3 = ex2f((S[nb][3] - mn1) * LOG2E);
                s0 += e0 + e1; s1 += e2 + e3;
                __half2 h01 = __floats2half2_rn(e0, e1);
                __half2 h23 = __floats2half2_rn(e2, e3);
                Ph[kk][2 * t + 0] = h2u(h01);
                Ph[kk][2 * t + 1] = h2u(h23);
                float2 f01 = __half22float2(h01), f23 = __half22float2(h23);
                Pl[kk][2 * t + 0] = h2u(__floats2half2_rn(e0 - f01.x, e1 - f01.y));
                Pl[kk][2 * t + 1] = h2u(__floats2half2_rn(e2 - f23.x, e3 - f23.y));
            }
        }
        s0 += __shfl_xor_sync(0xffffffffu, s0, 1);
        s0 += __shfl_xor_sync(0xffffffffu, s0, 2);
        s1 += __shfl_xor_sync(0xffffffffu, s1, 1);
        s1 += __shfl_xor_sync(0xffffffffu, s1, 2);
        l0 = l0 * c0 + s0;
        l1 = l1 * c1 + s1;

        #pragma unroll
        for (int nb = 0; nb < 8; ++nb) {
            O[nb][0] *= c0; O[nb][1] *= c0; O[nb][2] *= c1; O[nb][3] *= c1;
        }

        // ---- GEMM2: O(16x64) += Phi*Vhi + Plo*Vhi + Phi*Vlo ----
        #pragma unroll
        for (int kk = 0; kk < 4; ++kk) {
            #pragma unroll
            for (int nb = 0; nb < 8; ++nb) {
                uint32_t ao = kb + (uint32_t)(((nb * 8 + q4) * VSTR + kk * 16 + qm * 2) * 2);
                uint32_t bh[2], bl[2];
                bh[0] = lds32(ao + OFF_VHI);  bh[1] = lds32(ao + OFF_VHI + 16);
                bl[0] = lds32(ao + OFF_VLO);  bl[1] = lds32(ao + OFF_VLO + 16);
                mma16816(O[nb], Ph[kk], bh);
                mma16816(O[nb], Pl[kk], bh);
                mma16816(O[nb], Ph[kk], bl);
            }
        }
        __syncthreads();
    }

    // ---- epilogue: out = gamma * (O / l) + x ----
    const float inv0 = 1.0f / l0, inv1 = 1.0f / l1;
    const float gm = __ldg(gamma_p);
    const float* xb = x   + (size_t)b * NPOS * CH;
    float*       ob = out + (size_t)b * NPOS * CH;
    const int gr0 = i0 + w * 16 + q4;
    const int gr1 = gr0 + 8;
    #pragma unroll
    for (int nb = 0; nb < 8; ++nb) {
        int c = nb * 8 + qm * 2;
        float2 xv0 = *(const float2*)(xb + (size_t)gr0 * CH + c);
        float2 xv1 = *(const float2*)(xb + (size_t)gr1 * CH + c);
        float2 o0, o1;
        o0.x = fmaf(gm, O[nb][0] * inv0, xv0.x);
        o0.y = fmaf(gm, O[nb][1] * inv0, xv0.y);
        o1.x = fmaf(gm, O[nb][2] * inv1, xv1.x);
        o1.y = fmaf(gm, O[nb][3] * inv1, xv1.y);
        *(float2*)(ob + (size_t)gr0 * CH + c) = o0;
        *(float2*)(ob + (size_t)gr1 * CH + c) = o1;
    }
}

// ---------------- launch ----------------
extern "C" void kernel_launch(void* const* d_in, const int* in_sizes, int n_in,
                              void* d_out, int out_size)
{
    const float* x     = (const float*)d_in[0];
    const float* gamma = (const float*)d_in[1];
    float* out         = (float*)d_out;

    cudaFuncSetAttribute(attn_kernel,
                         cudaFuncAttributeMaxDynamicSharedMemorySize, SMEM_TOTAL);

    convert_kernel<<<dim3(NPOS / 64, 2), 256>>>(x);
    attn_kernel<<<dim3(NPOS / BM, 2), 128, SMEM_TOTAL>>>(x, gamma, out);
}

// round 6
// speedup vs baseline: 1.1265x; 1.1265x over previous
#include <cuda_runtime.h>
#include <cuda_fp16.h>
#include <cstdint>

#define NPOS 8192
#define CH 64
#define BM 64          // rows per group (4 warps x 16)
#define BN 64          // keys per tile
#define NT (NPOS / BN) // 128
#define LOG2E 1.4426950408889634f

// ---------------- device scratch ----------------
#define TOT_ELEMS (2 * NPOS * CH)
__device__ __half g_hi[TOT_ELEMS];    // [b][n][c] fp16 hi
__device__ __half g_lo[TOT_ELEMS];    // [b][n][c] fp16 lo residual

// ---------------- helpers ----------------
__device__ __forceinline__ uint32_t smem_u32(const void* p) {
    uint32_t a;
    asm("{ .reg .u64 t; cvta.to.shared.u64 t, %1; cvt.u32.u64 %0, t; }" : "=r"(a) : "l"(p));
    return a;
}
__device__ __forceinline__ float ex2f(float v) {
    float r; asm("ex2.approx.ftz.f32 %0, %1;" : "=f"(r) : "f"(v)); return r;
}
__device__ __forceinline__ uint32_t h2u(__half2 h) { return *reinterpret_cast<uint32_t*>(&h); }

__device__ __forceinline__ void cp_async16(uint32_t dst, const void* src) {
    asm volatile("cp.async.cg.shared.global [%0], [%1], 16;" :: "r"(dst), "l"(src) : "memory");
}
__device__ __forceinline__ void cp_commit() {
    asm volatile("cp.async.commit_group;" ::: "memory");
}
template <int N>
__device__ __forceinline__ void cp_wait() {
    asm volatile("cp.async.wait_group %0;" :: "n"(N) : "memory");
}
#define GRP_BAR(id) asm volatile("bar.sync %0, 128;" :: "r"(id) : "memory")

__device__ __forceinline__ void ldsm_x4(uint32_t* r, uint32_t addr) {
    asm volatile("ldmatrix.sync.aligned.m8n8.x4.shared.b16 {%0,%1,%2,%3}, [%4];"
        : "=r"(r[0]), "=r"(r[1]), "=r"(r[2]), "=r"(r[3]) : "r"(addr));
}
__device__ __forceinline__ void ldsm_x4_trans(uint32_t* r, uint32_t addr) {
    asm volatile("ldmatrix.sync.aligned.m8n8.x4.trans.shared.b16 {%0,%1,%2,%3}, [%4];"
        : "=r"(r[0]), "=r"(r[1]), "=r"(r[2]), "=r"(r[3]) : "r"(addr));
}

// mma.sync m16n8k16 f16 -> f32 accumulate
__device__ __forceinline__ void mma16816(float* d, const uint32_t* a, const uint32_t* b) {
    asm volatile(
        "mma.sync.aligned.m16n8k16.row.col.f32.f16.f16.f32 "
        "{%0,%1,%2,%3}, {%4,%5,%6,%7}, {%8,%9}, {%0,%1,%2,%3};"
        : "+f"(d[0]), "+f"(d[1]), "+f"(d[2]), "+f"(d[3])
        : "r"(a[0]), "r"(a[1]), "r"(a[2]), "r"(a[3]), "r"(b[0]), "r"(b[1]));
}

// ---------------- smem layout ----------------
#define KSTR 72                         // K tile row stride in halfs (64 + 8 pad)
#define KTILE (BN * KSTR * 2)           // one hi or lo tile = 9216 B
#define BUFSZ (2 * KTILE)               // hi + lo = 18432 B
#define GRPSZ (2 * BUFSZ)               // double-buffered = 36864 B
#define SMEM_TOTAL (2 * GRPSZ)          // two groups = 73728 B

// ---------------- pre-pass: fp32 -> fp16 hi/lo ----------------
__global__ __launch_bounds__(256) void convert_kernel(const float* __restrict__ x)
{
    size_t i4 = ((size_t)blockIdx.x * 256 + threadIdx.x) * 4;
    float4 v = *(const float4*)(x + i4);
    __half h0 = __float2half_rn(v.x), h1 = __float2half_rn(v.y);
    __half h2 = __float2half_rn(v.z), h3 = __float2half_rn(v.w);
    uint2 hw = make_uint2(h2u(__halves2half2(h0, h1)), h2u(__halves2half2(h2, h3)));
    *(uint2*)(g_hi + i4) = hw;
    __half l0 = __float2half_rn(v.x - __half2float(h0));
    __half l1 = __float2half_rn(v.y - __half2float(h1));
    __half l2 = __float2half_rn(v.z - __half2float(h2));
    __half l3 = __float2half_rn(v.w - __half2float(h3));
    uint2 lw = make_uint2(h2u(__halves2half2(l0, l1)), h2u(__halves2half2(l2, l3)));
    *(uint2*)(g_lo + i4) = lw;
}

// ---------------- main kernel: 2 batch-groups per CTA ----------------
__global__ __launch_bounds__(256, 1) void attn_kernel(
    const float* __restrict__ x,
    const float* __restrict__ gamma_p,
    float* __restrict__ out)
{
    extern __shared__ __align__(128) char smem[];
    const uint32_t sb = smem_u32(smem);
    const int tid  = threadIdx.x;
    const int w    = tid >> 5;
    const int lane = tid & 31;
    const int q4   = lane >> 2;
    const int qm   = lane & 3;
    const int grp  = w >> 2;          // 0 -> batch 0, 1 -> batch 1
    const int wg   = w & 3;           // warp within group
    const int gtid = tid & 127;
    const int b    = grp;
    const int i0   = blockIdx.x * BM;

    const __half* xhi = g_hi + (size_t)b * NPOS * CH;
    const __half* xlo = g_lo + (size_t)b * NPOS * CH;
    const uint32_t gbase = sb + (uint32_t)grp * GRPSZ;

    // ---- prefetch one K tile (hi+lo) into buffer `buf` ----
    auto prefetch = [&](int jt, int buf) {
        const uint32_t d = gbase + (uint32_t)buf * BUFSZ;
        const int j0 = jt * BN;
        #pragma unroll
        for (int it = 0; it < 4; ++it) {           // 64 rows x 8 chunks of 16B
            int lin = it * 128 + gtid;
            int row = lin >> 3, c16 = (lin & 7) * 8;
            uint32_t so = (uint32_t)(row * KSTR + c16) * 2;
            const size_t go = (size_t)(j0 + row) * CH + c16;
            cp_async16(d + so, xhi + go);
            cp_async16(d + KTILE + so, xlo + go);
        }
        cp_commit();
    };

    prefetch(0, 0);

    // ---- Q fragments (hi+lo), loaded once from gmem ----
    uint32_t Qh[4][4], Ql[4][4];
    {
        const int r0 = i0 + wg * 16 + q4;
        #pragma unroll
        for (int kc = 0; kc < 4; ++kc) {
            int c = kc * 16 + qm * 2;
            Qh[kc][0] = *(const uint32_t*)(xhi + (size_t)r0 * CH + c);
            Qh[kc][1] = *(const uint32_t*)(xhi + (size_t)(r0 + 8) * CH + c);
            Qh[kc][2] = *(const uint32_t*)(xhi + (size_t)r0 * CH + c + 8);
            Qh[kc][3] = *(const uint32_t*)(xhi + (size_t)(r0 + 8) * CH + c + 8);
            Ql[kc][0] = *(const uint32_t*)(xlo + (size_t)r0 * CH + c);
            Ql[kc][1] = *(const uint32_t*)(xlo + (size_t)(r0 + 8) * CH + c);
            Ql[kc][2] = *(const uint32_t*)(xlo + (size_t)r0 * CH + c + 8);
            Ql[kc][3] = *(const uint32_t*)(xlo + (size_t)(r0 + 8) * CH + c + 8);
        }
    }

    // ldmatrix per-lane address offsets (within a tile)
    // GEMM1 (non-trans): m = lane>>3; row j += ((m>>1)&1)*8 + (lane&7); col c += (m&1)*8
    const uint32_t aoff1 = (uint32_t)((((lane >> 4) & 1) * 8 + (lane & 7)) * KSTR
                                      + ((lane >> 3) & 1) * 8) * 2;
    // GEMM2 (trans):    m = lane>>3; row j += (m&1)*8 + (lane&7); col c += ((m>>1)&1)*8
    const uint32_t aoff2 = (uint32_t)(((( lane >> 3) & 1) * 8 + (lane & 7)) * KSTR
                                      + ((lane >> 4) & 1) * 8) * 2;

    float m0 = -1e30f, m1 = -1e30f, l0 = 0.0f, l1 = 0.0f;
    float O[8][4];
    #pragma unroll
    for (int nb = 0; nb < 8; ++nb)
        #pragma unroll
        for (int e = 0; e < 4; ++e) O[nb][e] = 0.0f;

    const int barid = 1 + grp;

    for (int jt = 0; jt < NT; ++jt) {
        if (jt + 1 < NT) { prefetch(jt + 1, (jt + 1) & 1); cp_wait<1>(); }
        else             { cp_wait<0>(); }
        GRP_BAR(barid);

        const uint32_t kb = gbase + (uint32_t)(jt & 1) * BUFSZ;

        // ---- GEMM1: S(16x64) = Qhi*Khi + Qlo*Khi + Qhi*Klo ----
        float S[8][4];
        #pragma unroll
        for (int nb = 0; nb < 8; ++nb)
            #pragma unroll
            for (int e = 0; e < 4; ++e) S[nb][e] = 0.0f;

        #pragma unroll
        for (int kc = 0; kc < 4; ++kc) {
            #pragma unroll
            for (int jb = 0; jb < 4; ++jb) {
                uint32_t a = kb + aoff1 + (uint32_t)((jb * 16 * KSTR + kc * 16) * 2);
                uint32_t bh[4], bl[4];
                ldsm_x4(bh, a);
                ldsm_x4(bl, a + KTILE);
                mma16816(S[jb * 2],     Qh[kc], bh);
                mma16816(S[jb * 2],     Ql[kc], bh);
                mma16816(S[jb * 2],     Qh[kc], bl);
                mma16816(S[jb * 2 + 1], Qh[kc], bh + 2);
                mma16816(S[jb * 2 + 1], Ql[kc], bh + 2);
                mma16816(S[jb * 2 + 1], Qh[kc], bl + 2);
            }
        }

        // ---- online softmax ----
        float mx0 = -1e30f, mx1 = -1e30f;
        #pragma unroll
        for (int nb = 0; nb < 8; ++nb) {
            mx0 = fmaxf(mx0, fmaxf(S[nb][0], S[nb][1]));
            mx1 = fmaxf(mx1, fmaxf(S[nb][2], S[nb][3]));
        }
        mx0 = fmaxf(mx0, __shfl_xor_sync(0xffffffffu, mx0, 1));
        mx0 = fmaxf(mx0, __shfl_xor_sync(0xffffffffu, mx0, 2));
        mx1 = fmaxf(mx1, __shfl_xor_sync(0xffffffffu, mx1, 1));
        mx1 = fmaxf(mx1, __shfl_xor_sync(0xffffffffu, mx1, 2));
        float mn0 = fmaxf(m0, mx0), mn1 = fmaxf(m1, mx1);
        float c0 = ex2f((m0 - mn0) * LOG2E), c1 = ex2f((m1 - mn1) * LOG2E);
        m0 = mn0; m1 = mn1;

        float s0 = 0.0f, s1 = 0.0f;
        uint32_t Ph[4][4], Pl[4][4];
        #pragma unroll
        for (int kk = 0; kk < 4; ++kk) {
            #pragma unroll
            for (int t = 0; t < 2; ++t) {
                int nb = 2 * kk + t;
                float e0 = ex2f((S[nb][0] - mn0) * LOG2E);
                float e1 = ex2f((S[nb][1] - mn0) * LOG2E);
                float e2 = ex2f((S[nb][2] - mn1) * LOG2E);
                float e3 = ex2f((S[nb][3] - mn1) * LOG2E);
                s0 += e0 + e1; s1 += e2 + e3;
                __half2 h01 = __floats2half2_rn(e0, e1);
                __half2 h23 = __floats2half2_rn(e2, e3);
                Ph[kk][2 * t + 0] = h2u(h01);
                Ph[kk][2 * t + 1] = h2u(h23);
                float2 f01 = __half22float2(h01), f23 = __half22float2(h23);
                Pl[kk][2 * t + 0] = h2u(__floats2half2_rn(e0 - f01.x, e1 - f01.y));
                Pl[kk][2 * t + 1] = h2u(__floats2half2_rn(e2 - f23.x, e3 - f23.y));
            }
        }
        s0 += __shfl_xor_sync(0xffffffffu, s0, 1);
        s0 += __shfl_xor_sync(0xffffffffu, s0, 2);
        s1 += __shfl_xor_sync(0xffffffffu, s1, 1);
        s1 += __shfl_xor_sync(0xffffffffu, s1, 2);
        l0 = l0 * c0 + s0;
        l1 = l1 * c1 + s1;

        #pragma unroll
        for (int nb = 0; nb < 8; ++nb) {
            O[nb][0] *= c0; O[nb][1] *= c0; O[nb][2] *= c1; O[nb][3] *= c1;
        }

        // ---- GEMM2: O(16x64) += Phi*Vhi + Plo*Vhi + Phi*Vlo  (V = K tile, trans-ldmatrix) ----
        #pragma unroll
        for (int kk = 0; kk < 4; ++kk) {
            #pragma unroll
            for (int cb = 0; cb < 4; ++cb) {
                uint32_t a = kb + aoff2 + (uint32_t)((kk * 16 * KSTR + cb * 16) * 2);
                uint32_t bh[4], bl[4];
                ldsm_x4_trans(bh, a);
                ldsm_x4_trans(bl, a + KTILE);
                mma16816(O[cb * 2],     Ph[kk], bh);
                mma16816(O[cb * 2],     Pl[kk], bh);
                mma16816(O[cb * 2],     Ph[kk], bl);
                mma16816(O[cb * 2 + 1], Ph[kk], bh + 2);
                mma16816(O[cb * 2 + 1], Pl[kk], bh + 2);
                mma16816(O[cb * 2 + 1], Ph[kk], bl + 2);
            }
        }
        GRP_BAR(barid);
    }

    // ---- epilogue: out = gamma * (O / l) + x ----
    const float inv0 = 1.0f / l0, inv1 = 1.0f / l1;
    const float gm = __ldg(gamma_p);
    const float* xb = x   + (size_t)b * NPOS * CH;
    float*       ob = out + (size_t)b * NPOS * CH;
    const int gr0 = i0 + wg * 16 + q4;
    const int gr1 = gr0 + 8;
    #pragma unroll
    for (int nb = 0; nb < 8; ++nb) {
        int c = nb * 8 + qm * 2;
        float2 xv0 = *(const float2*)(xb + (size_t)gr0 * CH + c);
        float2 xv1 = *(const float2*)(xb + (size_t)gr1 * CH + c);
        float2 o0, o1;
        o0.x = fmaf(gm, O[nb][0] * inv0, xv0.x);
        o0.y = fmaf(gm, O[nb][1] * inv0, xv0.y);
        o1.x = fmaf(gm, O[nb][2] * inv1, xv1.x);
        o1.y = fmaf(gm, O[nb][3] * inv1, xv1.y);
        *(float2*)(ob + (size_t)gr0 * CH + c) = o0;
        *(float2*)(ob + (size_t)gr1 * CH + c) = o1;
    }
}

// ---------------- launch ----------------
extern "C" void kernel_launch(void* const* d_in, const int* in_sizes, int n_in,
                              void* d_out, int out_size)
{
    const float* x     = (const float*)d_in[0];
    const float* gamma = (const float*)d_in[1];
    float* out         = (float*)d_out;

    cudaFuncSetAttribute(attn_kernel,
                         cudaFuncAttributeMaxDynamicSharedMemorySize, SMEM_TOTAL);

    convert_kernel<<<TOT_ELEMS / (256 * 4), 256>>>(x);
    attn_kernel<<<NPOS / BM, 256, SMEM_TOTAL>>>(x, gamma, out);
}

// round 7
// speedup vs baseline: 1.5918x; 1.4132x over previous
#include <cuda_runtime.h>
#include <cuda_fp16.h>
#include <cstdint>

#define NPOS 8192
#define CH 64
#define BM 64          // rows per group (4 warps x 16)
#define BN 64          // keys per tile
#define NT (NPOS / BN) // 128
#define LOG2E 1.4426950408889634f

// ---------------- device scratch ----------------
#define TOT_ELEMS (2 * NPOS * CH)
__device__ __half g_hi[TOT_ELEMS];    // [b][n][c] fp16 hi
__device__ __half g_lo[TOT_ELEMS];    // [b][n][c] fp16 lo residual

// ---------------- helpers ----------------
__device__ __forceinline__ uint32_t smem_u32(const void* p) {
    uint32_t a;
    asm("{ .reg .u64 t; cvta.to.shared.u64 t, %1; cvt.u32.u64 %0, t; }" : "=r"(a) : "l"(p));
    return a;
}
__device__ __forceinline__ float ex2f(float v) {
    float r; asm("ex2.approx.ftz.f32 %0, %1;" : "=f"(r) : "f"(v)); return r;
}
__device__ __forceinline__ uint32_t h2u(__half2 h) { return *reinterpret_cast<uint32_t*>(&h); }

__device__ __forceinline__ void cp_async16(uint32_t dst, const void* src) {
    asm volatile("cp.async.cg.shared.global [%0], [%1], 16;" :: "r"(dst), "l"(src) : "memory");
}
__device__ __forceinline__ void cp_commit() {
    asm volatile("cp.async.commit_group;" ::: "memory");
}
template <int N>
__device__ __forceinline__ void cp_wait() {
    asm volatile("cp.async.wait_group %0;" :: "n"(N) : "memory");
}
#define GRP_BAR(id) asm volatile("bar.sync %0, 128;" :: "r"(id) : "memory")
#define STAG_ARRIVE() asm volatile("bar.arrive 3, 256;" ::: "memory")
#define STAG_WAIT()   asm volatile("bar.sync 3, 256;" ::: "memory")

__device__ __forceinline__ void ldsm_x4(uint32_t* r, uint32_t addr) {
    asm volatile("ldmatrix.sync.aligned.m8n8.x4.shared.b16 {%0,%1,%2,%3}, [%4];"
        : "=r"(r[0]), "=r"(r[1]), "=r"(r[2]), "=r"(r[3]) : "r"(addr));
}
__device__ __forceinline__ void ldsm_x4_trans(uint32_t* r, uint32_t addr) {
    asm volatile("ldmatrix.sync.aligned.m8n8.x4.trans.shared.b16 {%0,%1,%2,%3}, [%4];"
        : "=r"(r[0]), "=r"(r[1]), "=r"(r[2]), "=r"(r[3]) : "r"(addr));
}

// mma.sync m16n8k16 f16 -> f32 accumulate
__device__ __forceinline__ void mma16816(float* d, const uint32_t* a, const uint32_t* b) {
    asm volatile(
        "mma.sync.aligned.m16n8k16.row.col.f32.f16.f16.f32 "
        "{%0,%1,%2,%3}, {%4,%5,%6,%7}, {%8,%9}, {%0,%1,%2,%3};"
        : "+f"(d[0]), "+f"(d[1]), "+f"(d[2]), "+f"(d[3])
        : "r"(a[0]), "r"(a[1]), "r"(a[2]), "r"(a[3]), "r"(b[0]), "r"(b[1]));
}

// ---------------- smem layout ----------------
#define KSTR 72                         // K tile row stride in halfs (64 + 8 pad)
#define KTILE (BN * KSTR * 2)           // one hi or lo tile = 9216 B
#define BUFSZ (2 * KTILE)               // hi + lo = 18432 B
#define GRPSZ (2 * BUFSZ)               // double-buffered = 36864 B
#define SMEM_TOTAL (2 * GRPSZ)          // two groups = 73728 B

// ---------------- pre-pass: fp32 -> fp16 hi/lo ----------------
__global__ __launch_bounds__(256) void convert_kernel(const float* __restrict__ x)
{
    size_t i4 = ((size_t)blockIdx.x * 256 + threadIdx.x) * 4;
    float4 v = *(const float4*)(x + i4);
    __half h0 = __float2half_rn(v.x), h1 = __float2half_rn(v.y);
    __half h2 = __float2half_rn(v.z), h3 = __float2half_rn(v.w);
    uint2 hw = make_uint2(h2u(__halves2half2(h0, h1)), h2u(__halves2half2(h2, h3)));
    *(uint2*)(g_hi + i4) = hw;
    __half l0 = __float2half_rn(v.x - __half2float(h0));
    __half l1 = __float2half_rn(v.y - __half2float(h1));
    __half l2 = __float2half_rn(v.z - __half2float(h2));
    __half l3 = __float2half_rn(v.w - __half2float(h3));
    uint2 lw = make_uint2(h2u(__halves2half2(l0, l1)), h2u(__halves2half2(l2, l3)));
    *(uint2*)(g_lo + i4) = lw;
}

// ---------------- main kernel: 2 batch-groups per CTA, phase-staggered ----------------
__global__ __launch_bounds__(256, 1) void attn_kernel(
    const float* __restrict__ x,
    const float* __restrict__ gamma_p,
    float* __restrict__ out)
{
    extern __shared__ __align__(128) char smem[];
    const uint32_t sb = smem_u32(smem);
    const int tid  = threadIdx.x;
    const int w    = tid >> 5;
    const int lane = tid & 31;
    const int q4   = lane >> 2;
    const int qm   = lane & 3;
    const int grp  = w >> 2;          // 0 -> batch 0, 1 -> batch 1
    const int wg   = w & 3;           // warp within group
    const int gtid = tid & 127;
    const int b    = grp;
    const int i0   = blockIdx.x * BM;

    const __half* xhi = g_hi + (size_t)b * NPOS * CH;
    const __half* xlo = g_lo + (size_t)b * NPOS * CH;
    const uint32_t gbase = sb + (uint32_t)grp * GRPSZ;

    // ---- prefetch one K tile (hi+lo) into buffer `buf` ----
    auto prefetch = [&](int jt, int buf) {
        const uint32_t d = gbase + (uint32_t)buf * BUFSZ;
        const int j0 = jt * BN;
        #pragma unroll
        for (int it = 0; it < 4; ++it) {           // 64 rows x 8 chunks of 16B
            int lin = it * 128 + gtid;
            int row = lin >> 3, c16 = (lin & 7) * 8;
            uint32_t so = (uint32_t)(row * KSTR + c16) * 2;
            const size_t go = (size_t)(j0 + row) * CH + c16;
            cp_async16(d + so, xhi + go);
            cp_async16(d + KTILE + so, xlo + go);
        }
        cp_commit();
    };

    prefetch(0, 0);

    // ---- Q fragments (hi only; Qlo dropped per error analysis) ----
    uint32_t Qh[4][4];
    {
        const int r0 = i0 + wg * 16 + q4;
        #pragma unroll
        for (int kc = 0; kc < 4; ++kc) {
            int c = kc * 16 + qm * 2;
            Qh[kc][0] = *(const uint32_t*)(xhi + (size_t)r0 * CH + c);
            Qh[kc][1] = *(const uint32_t*)(xhi + (size_t)(r0 + 8) * CH + c);
            Qh[kc][2] = *(const uint32_t*)(xhi + (size_t)r0 * CH + c + 8);
            Qh[kc][3] = *(const uint32_t*)(xhi + (size_t)(r0 + 8) * CH + c + 8);
        }
    }

    // ldmatrix per-lane address offsets (within a tile)
    const uint32_t aoff1 = (uint32_t)((((lane >> 4) & 1) * 8 + (lane & 7)) * KSTR
                                      + ((lane >> 3) & 1) * 8) * 2;
    const uint32_t aoff2 = (uint32_t)(((( lane >> 3) & 1) * 8 + (lane & 7)) * KSTR
                                      + ((lane >> 4) & 1) * 8) * 2;

    float m0 = -1e30f, m1 = -1e30f, l0 = 0.0f, l1 = 0.0f;
    float O[8][4];
    #pragma unroll
    for (int nb = 0; nb < 8; ++nb)
        #pragma unroll
        for (int e = 0; e < 4; ++e) O[nb][e] = 0.0f;

    const int barid = 1 + grp;

    for (int jt = 0; jt < NT; ++jt) {
        if (jt + 1 < NT) { prefetch(jt + 1, (jt + 1) & 1); cp_wait<1>(); }
        else             { cp_wait<0>(); }
        GRP_BAR(barid);

        // one-time phase stagger: group 1 holds until group 0 clears GEMM1+softmax of tile 0
        if (jt == 0 && grp == 1) STAG_WAIT();

        const uint32_t kb = gbase + (uint32_t)(jt & 1) * BUFSZ;

        // ---- GEMM1: S(16x64) = Qhi*Khi + Qhi*Klo ----
        float S[8][4];
        #pragma unroll
        for (int nb = 0; nb < 8; ++nb)
            #pragma unroll
            for (int e = 0; e < 4; ++e) S[nb][e] = 0.0f;

        #pragma unroll
        for (int kc = 0; kc < 4; ++kc) {
            #pragma unroll
            for (int jb = 0; jb < 4; ++jb) {
                uint32_t a = kb + aoff1 + (uint32_t)((jb * 16 * KSTR + kc * 16) * 2);
                uint32_t bh[4], bl[4];
                ldsm_x4(bh, a);
                ldsm_x4(bl, a + KTILE);
                mma16816(S[jb * 2],     Qh[kc], bh);
                mma16816(S[jb * 2],     Qh[kc], bl);
                mma16816(S[jb * 2 + 1], Qh[kc], bh + 2);
                mma16816(S[jb * 2 + 1], Qh[kc], bl + 2);
            }
        }

        // ---- online softmax ----
        float mx0 = -1e30f, mx1 = -1e30f;
        #pragma unroll
        for (int nb = 0; nb < 8; ++nb) {
            mx0 = fmaxf(mx0, fmaxf(S[nb][0], S[nb][1]));
            mx1 = fmaxf(mx1, fmaxf(S[nb][2], S[nb][3]));
        }
        mx0 = fmaxf(mx0, __shfl_xor_sync(0xffffffffu, mx0, 1));
        mx0 = fmaxf(mx0, __shfl_xor_sync(0xffffffffu, mx0, 2));
        mx1 = fmaxf(mx1, __shfl_xor_sync(0xffffffffu, mx1, 1));
        mx1 = fmaxf(mx1, __shfl_xor_sync(0xffffffffu, mx1, 2));
        float mn0 = fmaxf(m0, mx0), mn1 = fmaxf(m1, mx1);
        float c0 = ex2f((m0 - mn0) * LOG2E), c1 = ex2f((m1 - mn1) * LOG2E);
        m0 = mn0; m1 = mn1;

        float s0 = 0.0f, s1 = 0.0f;
        uint32_t Ph[4][4];
        #pragma unroll
        for (int kk = 0; kk < 4; ++kk) {
            #pragma unroll
            for (int t = 0; t < 2; ++t) {
                int nb = 2 * kk + t;
                float e0 = ex2f((S[nb][0] - mn0) * LOG2E);
                float e1 = ex2f((S[nb][1] - mn0) * LOG2E);
                float e2 = ex2f((S[nb][2] - mn1) * LOG2E);
                float e3 = ex2f((S[nb][3] - mn1) * LOG2E);
                s0 += e0 + e1; s1 += e2 + e3;
                Ph[kk][2 * t + 0] = h2u(__floats2half2_rn(e0, e1));
                Ph[kk][2 * t + 1] = h2u(__floats2half2_rn(e2, e3));
            }
        }
        s0 += __shfl_xor_sync(0xffffffffu, s0, 1);
        s0 += __shfl_xor_sync(0xffffffffu, s0, 2);
        s1 += __shfl_xor_sync(0xffffffffu, s1, 1);
        s1 += __shfl_xor_sync(0xffffffffu, s1, 2);
        l0 = l0 * c0 + s0;
        l1 = l1 * c1 + s1;

        #pragma unroll
        for (int nb = 0; nb < 8; ++nb) {
            O[nb][0] *= c0; O[nb][1] *= c0; O[nb][2] *= c1; O[nb][3] *= c1;
        }

        // release group 1 once group 0 is past its first softmax
        if (jt == 0 && grp == 0) STAG_ARRIVE();

        // ---- GEMM2: O(16x64) += Phi*Vhi + Phi*Vlo  (V = K tile, trans-ldmatrix) ----
        #pragma unroll
        for (int kk = 0; kk < 4; ++kk) {
            #pragma unroll
            for (int cb = 0; cb < 4; ++cb) {
                uint32_t a = kb + aoff2 + (uint32_t)((kk * 16 * KSTR + cb * 16) * 2);
                uint32_t bh[4], bl[4];
                ldsm_x4_trans(bh, a);
                ldsm_x4_trans(bl, a + KTILE);
                mma16816(O[cb * 2],     Ph[kk], bh);
                mma16816(O[cb * 2],     Ph[kk], bl);
                mma16816(O[cb * 2 + 1], Ph[kk], bh + 2);
                mma16816(O[cb * 2 + 1], Ph[kk], bl + 2);
            }
        }
        GRP_BAR(barid);
    }

    // ---- epilogue: out = gamma * (O / l) + x ----
    const float inv0 = 1.0f / l0, inv1 = 1.0f / l1;
    const float gm = __ldg(gamma_p);
    const float* xb = x   + (size_t)b * NPOS * CH;
    float*       ob = out + (size_t)b * NPOS * CH;
    const int gr0 = i0 + wg * 16 + q4;
    const int gr1 = gr0 + 8;
    #pragma unroll
    for (int nb = 0; nb < 8; ++nb) {
        int c = nb * 8 + qm * 2;
        float2 xv0 = *(const float2*)(xb + (size_t)gr0 * CH + c);
        float2 xv1 = *(const float2*)(xb + (size_t)gr1 * CH + c);
        float2 o0, o1;
        o0.x = fmaf(gm, O[nb][0] * inv0, xv0.x);
        o0.y = fmaf(gm, O[nb][1] * inv0, xv0.y);
        o1.x = fmaf(gm, O[nb][2] * inv1, xv1.x);
        o1.y = fmaf(gm, O[nb][3] * inv1, xv1.y);
        *(float2*)(ob + (size_t)gr0 * CH + c) = o0;
        *(float2*)(ob + (size_t)gr1 * CH + c) = o1;
    }
}

// ---------------- launch ----------------
extern "C" void kernel_launch(void* const* d_in, const int* in_sizes, int n_in,
                              void* d_out, int out_size)
{
    const float* x     = (const float*)d_in[0];
    const float* gamma = (const float*)d_in[1];
    float* out         = (float*)d_out;

    cudaFuncSetAttribute(attn_kernel,
                         cudaFuncAttributeMaxDynamicSharedMemorySize, SMEM_TOTAL);

    convert_kernel<<<TOT_ELEMS / (256 * 4), 256>>>(x);
    attn_kernel<<<NPOS / BM, 256, SMEM_TOTAL>>>(x, gamma, out);
}

// round 9
// speedup vs baseline: 1.9602x; 1.2314x over previous
#include <cuda_runtime.h>
#include <cuda_fp16.h>
#include <cstdint>

#define NPOS 8192
#define CH 64
#define BM 64          // q-rows per group (4 warps x 16); CTA covers 2*BM = 128 rows
#define BN 128         // keys per tile
#define NT (NPOS / BN) // 64
#define LOG2E 1.4426950408889634f

// ---------------- device scratch ----------------
#define TOT_ELEMS (2 * NPOS * CH)
__device__ __half g_hi[TOT_ELEMS];    // [b][n][c] fp16 hi
__device__ __half g_lo[TOT_ELEMS];    // [b][n][c] fp16 lo residual

// ---------------- helpers ----------------
__device__ __forceinline__ uint32_t smem_u32(const void* p) {
    uint32_t a;
    asm("{ .reg .u64 t; cvta.to.shared.u64 t, %1; cvt.u32.u64 %0, t; }" : "=r"(a) : "l"(p));
    return a;
}
__device__ __forceinline__ float ex2f(float v) {
    float r; asm("ex2.approx.ftz.f32 %0, %1;" : "=f"(r) : "f"(v)); return r;
}
__device__ __forceinline__ uint32_t h2u(__half2 h) { return *reinterpret_cast<uint32_t*>(&h); }

__device__ __forceinline__ void cp_async16(uint32_t dst, const void* src) {
    asm volatile("cp.async.cg.shared.global [%0], [%1], 16;" :: "r"(dst), "l"(src) : "memory");
}
__device__ __forceinline__ void cp_commit() {
    asm volatile("cp.async.commit_group;" ::: "memory");
}
template <int N>
__device__ __forceinline__ void cp_wait() {
    asm volatile("cp.async.wait_group %0;" :: "n"(N) : "memory");
}

__device__ __forceinline__ void ldsm_x4(uint32_t* r, uint32_t addr) {
    asm volatile("ldmatrix.sync.aligned.m8n8.x4.shared.b16 {%0,%1,%2,%3}, [%4];"
        : "=r"(r[0]), "=r"(r[1]), "=r"(r[2]), "=r"(r[3]) : "r"(addr));
}
__device__ __forceinline__ void ldsm_x4_trans(uint32_t* r, uint32_t addr) {
    asm volatile("ldmatrix.sync.aligned.m8n8.x4.trans.shared.b16 {%0,%1,%2,%3}, [%4];"
        : "=r"(r[0]), "=r"(r[1]), "=r"(r[2]), "=r"(r[3]) : "r"(addr));
}

// mma.sync m16n8k16 f16 -> f32 accumulate
__device__ __forceinline__ void mma16816(float* d, const uint32_t* a, const uint32_t* b) {
    asm volatile(
        "mma.sync.aligned.m16n8k16.row.col.f32.f16.f16.f32 "
        "{%0,%1,%2,%3}, {%4,%5,%6,%7}, {%8,%9}, {%0,%1,%2,%3};"
        : "+f"(d[0]), "+f"(d[1]), "+f"(d[2]), "+f"(d[3])
        : "r"(a[0]), "r"(a[1]), "r"(a[2]), "r"(a[3]), "r"(b[0]), "r"(b[1]));
}

// ---------------- smem layout ----------------
#define KSTR 72                         // row stride in halfs (64 + 8 pad)
#define KTILE (BN * KSTR * 2)           // one hi or lo tile = 18432 B
#define BUFSZ (2 * KTILE)               // hi + lo = 36864 B
#define SMEM_TOTAL (3 * BUFSZ)          // triple-buffered = 110592 B (1 CTA/SM)

// ---------------- pre-pass: fp32 -> fp16 hi/lo ----------------
__global__ __launch_bounds__(256) void convert_kernel(const float* __restrict__ x)
{
    size_t i4 = ((size_t)blockIdx.x * 256 + threadIdx.x) * 4;
    float4 v = *(const float4*)(x + i4);
    __half h0 = __float2half_rn(v.x), h1 = __float2half_rn(v.y);
    __half h2 = __float2half_rn(v.z), h3 = __float2half_rn(v.w);
    uint2 hw = make_uint2(h2u(__halves2half2(h0, h1)), h2u(__halves2half2(h2, h3)));
    *(uint2*)(g_hi + i4) = hw;
    __half l0 = __float2half_rn(v.x - __half2float(h0));
    __half l1 = __float2half_rn(v.y - __half2float(h1));
    __half l2 = __float2half_rn(v.z - __half2float(h2));
    __half l3 = __float2half_rn(v.w - __half2float(h3));
    uint2 lw = make_uint2(h2u(__halves2half2(l0, l1)), h2u(__halves2half2(l2, l3)));
    *(uint2*)(g_lo + i4) = lw;
}

// ---------------- main kernel: 2 q-groups per CTA sharing K tiles ----------------
__global__ __launch_bounds__(256, 1) void attn_kernel(
    const float* __restrict__ x,
    const float* __restrict__ gamma_p,
    float* __restrict__ out)
{
    extern __shared__ __align__(128) char smem[];
    const uint32_t sb = smem_u32(smem);
    const int tid  = threadIdx.x;
    const int w    = tid >> 5;
    const int lane = tid & 31;
    const int q4   = lane >> 2;
    const int qm   = lane & 3;
    const int grp  = w >> 2;          // q-subtile within CTA
    const int wg   = w & 3;           // warp within group
    const int b    = blockIdx.y;
    const int i0   = blockIdx.x * (2 * BM) + grp * BM;

    const __half* xhi = g_hi + (size_t)b * NPOS * CH;
    const __half* xlo = g_lo + (size_t)b * NPOS * CH;

    // ---- prefetch one shared K tile (hi+lo), all 256 threads ----
    auto prefetch = [&](int jt, int buf) {
        const uint32_t d = sb + (uint32_t)buf * BUFSZ;
        const int j0 = jt * BN;
        #pragma unroll
        for (int it = 0; it < 4; ++it) {           // 128 rows x 8 chunks of 16B
            int lin = it * 256 + tid;
            int row = lin >> 3, c16 = (lin & 7) * 8;
            uint32_t so = (uint32_t)(row * KSTR + c16) * 2;
            const size_t go = (size_t)(j0 + row) * CH + c16;
            cp_async16(d + so, xhi + go);
            cp_async16(d + KTILE + so, xlo + go);
        }
        cp_commit();
    };

    prefetch(0, 0);

    // ---- Q fragments (hi only) ----
    uint32_t Qh[4][4];
    {
        const int r0 = i0 + wg * 16 + q4;
        #pragma unroll
        for (int kc = 0; kc < 4; ++kc) {
            int c = kc * 16 + qm * 2;
            Qh[kc][0] = *(const uint32_t*)(xhi + (size_t)r0 * CH + c);
            Qh[kc][1] = *(const uint32_t*)(xhi + (size_t)(r0 + 8) * CH + c);
            Qh[kc][2] = *(const uint32_t*)(xhi + (size_t)r0 * CH + c + 8);
            Qh[kc][3] = *(const uint32_t*)(xhi + (size_t)(r0 + 8) * CH + c + 8);
        }
    }

    // ldmatrix per-lane address offsets (within a tile)
    const uint32_t aoff1 = (uint32_t)((((lane >> 4) & 1) * 8 + (lane & 7)) * KSTR
                                      + ((lane >> 3) & 1) * 8) * 2;
    const uint32_t aoff2 = (uint32_t)(((( lane >> 3) & 1) * 8 + (lane & 7)) * KSTR
                                      + ((lane >> 4) & 1) * 8) * 2;

    float m0 = -1e30f, m1 = -1e30f, l0 = 0.0f, l1 = 0.0f;
    float O[8][4];
    #pragma unroll
    for (int nb = 0; nb < 8; ++nb)
        #pragma unroll
        for (int e = 0; e < 4; ++e) O[nb][e] = 0.0f;

    for (int jt = 0; jt < NT; ++jt) {
        if (jt + 1 < NT) { prefetch(jt + 1, (jt + 1) % 3); cp_wait<1>(); }
        else             { cp_wait<0>(); }
        __syncthreads();

        const uint32_t kb = sb + (uint32_t)(jt % 3) * BUFSZ;

        // ---- GEMM1: S(16x128) = Qhi*Khi + Qhi*Klo ----
        float S[16][4];
        #pragma unroll
        for (int nb = 0; nb < 16; ++nb)
            #pragma unroll
            for (int e = 0; e < 4; ++e) S[nb][e] = 0.0f;

        #pragma unroll
        for (int kc = 0; kc < 4; ++kc) {
            #pragma unroll
            for (int jb = 0; jb < 8; ++jb) {
                uint32_t a = kb + aoff1 + (uint32_t)((jb * 16 * KSTR + kc * 16) * 2);
                uint32_t bh[4], bl[4];
                ldsm_x4(bh, a);
                ldsm_x4(bl, a + KTILE);
                mma16816(S[jb * 2],     Qh[kc], bh);
                mma16816(S[jb * 2],     Qh[kc], bl);
                mma16816(S[jb * 2 + 1], Qh[kc], bh + 2);
                mma16816(S[jb * 2 + 1], Qh[kc], bl + 2);
            }
        }

        // ---- online softmax ----
        float mx0 = -1e30f, mx1 = -1e30f;
        #pragma unroll
        for (int nb = 0; nb < 16; ++nb) {
            mx0 = fmaxf(mx0, fmaxf(S[nb][0], S[nb][1]));
            mx1 = fmaxf(mx1, fmaxf(S[nb][2], S[nb][3]));
        }
        mx0 = fmaxf(mx0, __shfl_xor_sync(0xffffffffu, mx0, 1));
        mx0 = fmaxf(mx0, __shfl_xor_sync(0xffffffffu, mx0, 2));
        mx1 = fmaxf(mx1, __shfl_xor_sync(0xffffffffu, mx1, 1));
        mx1 = fmaxf(mx1, __shfl_xor_sync(0xffffffffu, mx1, 2));
        float mn0 = fmaxf(m0, mx0), mn1 = fmaxf(m1, mx1);

        // rescale O only when the running max moved (rare: diagonal dominance)
        if (mn0 > m0 || mn1 > m1) {
            float c0 = ex2f((m0 - mn0) * LOG2E), c1 = ex2f((m1 - mn1) * LOG2E);
            l0 *= c0; l1 *= c1;
            #pragma unroll
            for (int nb = 0; nb < 8; ++nb) {
                O[nb][0] *= c0; O[nb][1] *= c0; O[nb][2] *= c1; O[nb][3] *= c1;
            }
            m0 = mn0; m1 = mn1;
        }

        float s0 = 0.0f, s1 = 0.0f;
        uint32_t Ph[8][4];
        #pragma unroll
        for (int kk = 0; kk < 8; ++kk) {
            #pragma unroll
            for (int t = 0; t < 2; ++t) {
                int nb = 2 * kk + t;
                float e0 = ex2f((S[nb][0] - m0) * LOG2E);
                float e1 = ex2f((S[nb][1] - m0) * LOG2E);
                float e2 = ex2f((S[nb][2] - m1) * LOG2E);
                float e3 = ex2f((S[nb][3] - m1) * LOG2E);
                s0 += e0 + e1; s1 += e2 + e3;
                Ph[kk][2 * t + 0] = h2u(__floats2half2_rn(e0, e1));
                Ph[kk][2 * t + 1] = h2u(__floats2half2_rn(e2, e3));
            }
        }
        s0 += __shfl_xor_sync(0xffffffffu, s0, 1);
        s0 += __shfl_xor_sync(0xffffffffu, s0, 2);
        s1 += __shfl_xor_sync(0xffffffffu, s1, 1);
        s1 += __shfl_xor_sync(0xffffffffu, s1, 2);
        l0 += s0;
        l1 += s1;

        // ---- GEMM2: O(16x64) += Phi*Vhi  (V = K tile, trans-ldmatrix) ----
        #pragma unroll
        for (int kk = 0; kk < 8; ++kk) {
            #pragma unroll
            for (int cb = 0; cb < 4; ++cb) {
                uint32_t a = kb + aoff2 + (uint32_t)((kk * 16 * KSTR + cb * 16) * 2);
                uint32_t bh[4];
                ldsm_x4_trans(bh, a);
                mma16816(O[cb * 2],     Ph[kk], bh);
                mma16816(O[cb * 2 + 1], Ph[kk], bh + 2);
            }
        }
    }

    // ---- epilogue: out = gamma * (O / l) + x ----
    const float inv0 = 1.0f / l0, inv1 = 1.0f / l1;
    const float gm = __ldg(gamma_p);
    const float* xb = x   + (size_t)b * NPOS * CH;
    float*       ob = out + (size_t)b * NPOS * CH;
    const int gr0 = i0 + wg * 16 + q4;
    const int gr1 = gr0 + 8;
    #pragma unroll
    for (int nb = 0; nb < 8; ++nb) {
        int c = nb * 8 + qm * 2;
        float2 xv0 = *(const float2*)(xb + (size_t)gr0 * CH + c);
        float2 xv1 = *(const float2*)(xb + (size_t)gr1 * CH + c);
        float2 o0, o1;
        o0.x = fmaf(gm, O[nb][0] * inv0, xv0.x);
        o0.y = fmaf(gm, O[nb][1] * inv0, xv0.y);
        o1.x = fmaf(gm, O[nb][2] * inv1, xv1.x);
        o1.y = fmaf(gm, O[nb][3] * inv1, xv1.y);
        *(float2*)(ob + (size_t)gr0 * CH + c) = o0;
        *(float2*)(ob + (size_t)gr1 * CH + c) = o1;
    }
}

// ---------------- launch ----------------
extern "C" void kernel_launch(void* const* d_in, const int* in_sizes, int n_in,
                              void* d_out, int out_size)
{
    const float* x     = (const float*)d_in[0];
    const float* gamma = (const float*)d_in[1];
    float* out         = (float*)d_out;

    cudaFuncSetAttribute(attn_kernel,
                         cudaFuncAttributeMaxDynamicSharedMemorySize, SMEM_TOTAL);

    convert_kernel<<<TOT_ELEMS / (256 * 4), 256>>>(x);
    attn_kernel<<<dim3(NPOS / (2 * BM), 2), 256, SMEM_TOTAL>>>(x, gamma, out);
}